// round 2
// baseline (speedup 1.0000x reference)
#include <cuda_runtime.h>
#include <cuda_bf16.h>

// Inputs (metadata order):
//   d_in[0] = x            float32 [65536]
//   d_in[1] = edge_weights float32 [16777216]
//   d_in[2] = bias         float32 [65536]
//   d_in[3] = src          int32   [16777216]
//   d_in[4] = dst          int32   [16777216]
// Output: float32 [65536],  out[i] = bias[i] + sum_{e: dst[e]==i} x[src[e]]*edge_weights[e]
//
// Strategy (R2):
//  - L2 transaction throughput is the bottleneck (ncu: L2=67%, DRAM=18%).
//  - x (256KB) nearly fits L1 (228KB). Keep it there: stream ew/src/dst with
//    evict-streaming (__ldcs) so they don't evict x; gather x with default policy.
//  - 8 independent gathers in flight per thread iteration (2x float4 groups)
//    to hide L2/DRAM latency (issue was 2.9%).

__global__ void init_out_kernel(const float* __restrict__ bias,
                                float* __restrict__ out, int n) {
    int i = blockIdx.x * blockDim.x + threadIdx.x;
    if (i < n) out[i] = bias[i];
}

__global__ __launch_bounds__(256) void scatter_kernel(
        const float* __restrict__ x,
        const float* __restrict__ ew,
        const int*   __restrict__ src,
        const int*   __restrict__ dst,
        float* __restrict__ out,
        int n) {
    const int n8 = n >> 3;   // groups of 8 edges
    const float4* __restrict__ ew4 = reinterpret_cast<const float4*>(ew);
    const int4*   __restrict__ s4  = reinterpret_cast<const int4*>(src);
    const int4*   __restrict__ d4  = reinterpret_cast<const int4*>(dst);

    const int stride = gridDim.x * blockDim.x;
    for (int i = blockIdx.x * blockDim.x + threadIdx.x; i < n8; i += stride) {
        // Streaming loads: evict-first so they don't displace x in L1.
        int4   sA = __ldcs(&s4[2 * i]);
        int4   sB = __ldcs(&s4[2 * i + 1]);
        float4 wA = __ldcs(&ew4[2 * i]);
        float4 wB = __ldcs(&ew4[2 * i + 1]);
        int4   dA = __ldcs(&d4[2 * i]);
        int4   dB = __ldcs(&d4[2 * i + 1]);

        // 8 independent gathers in flight (x should be L1-resident).
        float x0 = x[sA.x];
        float x1 = x[sA.y];
        float x2 = x[sA.z];
        float x3 = x[sA.w];
        float x4 = x[sB.x];
        float x5 = x[sB.y];
        float x6 = x[sB.z];
        float x7 = x[sB.w];

        // Fire-and-forget reductions (REDG.ADD.F32).
        atomicAdd(&out[dA.x], wA.x * x0);
        atomicAdd(&out[dA.y], wA.y * x1);
        atomicAdd(&out[dA.z], wA.z * x2);
        atomicAdd(&out[dA.w], wA.w * x3);
        atomicAdd(&out[dB.x], wB.x * x4);
        atomicAdd(&out[dB.y], wB.y * x5);
        atomicAdd(&out[dB.z], wB.z * x6);
        atomicAdd(&out[dB.w], wB.w * x7);
    }

    // Tail (n not divisible by 8): handle remaining edges scalar.
    int tail_start = n8 << 3;
    for (int e = tail_start + blockIdx.x * blockDim.x + threadIdx.x;
         e < n; e += stride) {
        atomicAdd(&out[dst[e]], ew[e] * x[src[e]]);
    }
}

extern "C" void kernel_launch(void* const* d_in, const int* in_sizes, int n_in,
                              void* d_out, int out_size) {
    const float* x    = (const float*)d_in[0];
    const float* ew   = (const float*)d_in[1];
    const float* bias = (const float*)d_in[2];
    const int*   src  = (const int*)d_in[3];
    const int*   dst  = (const int*)d_in[4];
    float* out = (float*)d_out;

    const int n_nodes = in_sizes[0];
    const int n_edges = in_sizes[1];

    // 1) out = bias
    {
        int threads = 256;
        int blocks  = (n_nodes + threads - 1) / threads;
        init_out_kernel<<<blocks, threads>>>(bias, out, n_nodes);
    }

    // 2) scatter-add over edges
    {
        int threads = 256;
        int blocks = 2048;
        int n8 = n_edges >> 3;
        int max_blocks = (n8 + threads - 1) / threads;
        if (blocks > max_blocks) blocks = max_blocks;
        if (blocks < 1) blocks = 1;
        scatter_kernel<<<blocks, threads>>>(x, ew, src, dst, out, n_edges);
    }
}

// round 3
// speedup vs baseline: 1.0899x; 1.0899x over previous
#include <cuda_runtime.h>
#include <cuda_bf16.h>

// Inputs (metadata order):
//   d_in[0] = x            float32 [65536]
//   d_in[1] = edge_weights float32 [16777216]
//   d_in[2] = bias         float32 [65536]
//   d_in[3] = src          int32   [16777216]
//   d_in[4] = dst          int32   [16777216]
// Output: float32 [65536],  out[i] = bias[i] + sum_{e: dst[e]==i} x[src[e]]*edge_weights[e]
//
// R3 strategy: the binding resource is per-SM LSU/L1tex cost of scalar random
// accesses (1 random LDG + 1 spread REDG per edge ~= 145us). Replace the
// random LDG gather with a shared-memory LDS (~10x cheaper per lane):
//   - 2 phases; phase p holds x[p*32768 .. p*32768+32767] in 128KB smem.
//   - each phase streams all edges (vectorized), gathers x via LDS, and fires
//     REDG only for edges whose src falls in the resident half.
// Streams are read twice (384MB) -- DRAM had 5x headroom.

#define HALF_NODES 32768
#define SMEM_BYTES (HALF_NODES * 4)

__global__ void init_out_kernel(const float* __restrict__ bias,
                                float* __restrict__ out, int n) {
    int i = blockIdx.x * blockDim.x + threadIdx.x;
    if (i < n) out[i] = bias[i];
}

// Generic fallback (any n_nodes): plain gather + atomic.
__global__ __launch_bounds__(256) void scatter_fallback_kernel(
        const float* __restrict__ x,
        const float* __restrict__ ew,
        const int*   __restrict__ src,
        const int*   __restrict__ dst,
        float* __restrict__ out,
        int n) {
    const int stride = gridDim.x * blockDim.x;
    for (int e = blockIdx.x * blockDim.x + threadIdx.x; e < n; e += stride) {
        atomicAdd(&out[dst[e]], ew[e] * __ldg(&x[src[e]]));
    }
}

// Specialized kernel for n_nodes == 65536.
__global__ __launch_bounds__(1024) void scatter_smem_kernel(
        const float* __restrict__ x,
        const float* __restrict__ ew,
        const int*   __restrict__ src,
        const int*   __restrict__ dst,
        float* __restrict__ out,
        int n) {
    extern __shared__ float sx[];   // 32768 floats = 128KB

    const int  n4      = n >> 2;
    const int  gstride = gridDim.x * blockDim.x;
    const int  gtid    = blockIdx.x * blockDim.x + threadIdx.x;

    const float4* __restrict__ ew4 = reinterpret_cast<const float4*>(ew);
    const int4*   __restrict__ s4  = reinterpret_cast<const int4*>(src);
    const int4*   __restrict__ d4  = reinterpret_cast<const int4*>(dst);

#pragma unroll
    for (int phase = 0; phase < 2; ++phase) {
        // Load this phase's half of x into smem (coalesced).
        const float* xh = x + phase * HALF_NODES;
        for (int i = threadIdx.x; i < HALF_NODES; i += blockDim.x)
            sx[i] = xh[i];
        __syncthreads();

        const int lo = phase * HALF_NODES;

        for (int i = gtid; i < n4; i += gstride) {
            int4   s = __ldcs(&s4[i]);
            float4 w = __ldcs(&ew4[i]);
            int4   d = __ldcs(&d4[i]);

            // LDS gathers (mask to half-range; result only used when in range).
            float x0 = sx[s.x & (HALF_NODES - 1)];
            float x1 = sx[s.y & (HALF_NODES - 1)];
            float x2 = sx[s.z & (HALF_NODES - 1)];
            float x3 = sx[s.w & (HALF_NODES - 1)];

            if ((s.x & ~(HALF_NODES - 1)) == lo) atomicAdd(&out[d.x], w.x * x0);
            if ((s.y & ~(HALF_NODES - 1)) == lo) atomicAdd(&out[d.y], w.y * x1);
            if ((s.z & ~(HALF_NODES - 1)) == lo) atomicAdd(&out[d.z], w.z * x2);
            if ((s.w & ~(HALF_NODES - 1)) == lo) atomicAdd(&out[d.w], w.w * x3);
        }

        // Tail edges (n % 4).
        for (int e = (n4 << 2) + gtid; e < n; e += gstride) {
            int s = src[e];
            if ((s & ~(HALF_NODES - 1)) == lo)
                atomicAdd(&out[dst[e]], ew[e] * sx[s & (HALF_NODES - 1)]);
        }

        __syncthreads();  // done with this half of smem before reloading
    }
}

extern "C" void kernel_launch(void* const* d_in, const int* in_sizes, int n_in,
                              void* d_out, int out_size) {
    const float* x    = (const float*)d_in[0];
    const float* ew   = (const float*)d_in[1];
    const float* bias = (const float*)d_in[2];
    const int*   src  = (const int*)d_in[3];
    const int*   dst  = (const int*)d_in[4];
    float* out = (float*)d_out;

    const int n_nodes = in_sizes[0];
    const int n_edges = in_sizes[1];

    // 1) out = bias
    {
        int threads = 256;
        int blocks  = (n_nodes + threads - 1) / threads;
        init_out_kernel<<<blocks, threads>>>(bias, out, n_nodes);
    }

    // 2) scatter-add
    if (n_nodes == 2 * HALF_NODES) {
        static bool attr_set = false;
        if (!attr_set) {
            cudaFuncSetAttribute(scatter_smem_kernel,
                                 cudaFuncAttributeMaxDynamicSharedMemorySize,
                                 SMEM_BYTES);
            attr_set = true;
        }
        int threads = 1024;
        int blocks  = 148;   // persistent: 1 CTA per SM (128KB smem each)
        scatter_smem_kernel<<<blocks, threads, SMEM_BYTES>>>(
            x, ew, src, dst, out, n_edges);
    } else {
        int threads = 256;
        int blocks  = 2048;
        int max_blocks = (n_edges + threads - 1) / threads;
        if (blocks > max_blocks) blocks = max_blocks;
        if (blocks < 1) blocks = 1;
        scatter_fallback_kernel<<<blocks, threads>>>(x, ew, src, dst, out, n_edges);
    }
}

// round 4
// speedup vs baseline: 1.1867x; 1.0888x over previous
#include <cuda_runtime.h>
#include <cuda_bf16.h>

// Inputs (metadata order):
//   d_in[0] = x            float32 [65536]
//   d_in[1] = edge_weights float32 [16777216]
//   d_in[2] = bias         float32 [65536]
//   d_in[3] = src          int32   [16777216]
//   d_in[4] = dst          int32   [16777216]
// Output: float32 [65536],  out[i] = bias[i] + sum_{e: dst[e]==i} x[src[e]]*edge_weights[e]
//
// R4: all prior rounds capped at ~64 fp32-RMW/cyc chip-wide into the 256KB
// output (8192 L2 sectors). Hypothesis: per-sector serialization at the LTS.
// Fix: 16 accumulator replicas (4MB scratch, L2-resident) -> 16x more target
// sectors -> atomics spread. Final kernel reduces replicas + bias.

#define NODES    65536
#define REPLICAS 16

__device__ float g_rep[REPLICAS * NODES];   // 4MB scratch (allowed: device global)

__global__ void zero_rep_kernel() {
    int i = blockIdx.x * blockDim.x + threadIdx.x;
    float4* p = reinterpret_cast<float4*>(g_rep);
    int n4 = (REPLICAS * NODES) / 4;
    if (i < n4) p[i] = make_float4(0.f, 0.f, 0.f, 0.f);
}

__global__ __launch_bounds__(256) void scatter_rep_kernel(
        const float* __restrict__ x,
        const float* __restrict__ ew,
        const int*   __restrict__ src,
        const int*   __restrict__ dst,
        int n) {
    const int n4 = n >> 2;
    const float4* __restrict__ ew4 = reinterpret_cast<const float4*>(ew);
    const int4*   __restrict__ s4  = reinterpret_cast<const int4*>(src);
    const int4*   __restrict__ d4  = reinterpret_cast<const int4*>(dst);

    // Replica choice: fixed per warp, decorrelated across warps and CTAs.
    const int warp_in_cta = threadIdx.x >> 5;
    float* rep = g_rep + ((blockIdx.x * 8 + warp_in_cta) & (REPLICAS - 1)) * NODES;

    const int stride = gridDim.x * blockDim.x;
    for (int i = blockIdx.x * blockDim.x + threadIdx.x; i < n4; i += stride) {
        int4   s = __ldcs(&s4[i]);
        float4 w = __ldcs(&ew4[i]);
        int4   d = __ldcs(&d4[i]);

        float x0 = __ldg(&x[s.x]);
        float x1 = __ldg(&x[s.y]);
        float x2 = __ldg(&x[s.z]);
        float x3 = __ldg(&x[s.w]);

        atomicAdd(&rep[d.x], w.x * x0);
        atomicAdd(&rep[d.y], w.y * x1);
        atomicAdd(&rep[d.z], w.z * x2);
        atomicAdd(&rep[d.w], w.w * x3);
    }

    // Tail (n % 4)
    for (int e = (n4 << 2) + blockIdx.x * blockDim.x + threadIdx.x;
         e < n; e += stride) {
        atomicAdd(&rep[dst[e]], ew[e] * __ldg(&x[src[e]]));
    }
}

__global__ void reduce_rep_kernel(const float* __restrict__ bias,
                                  float* __restrict__ out, int n) {
    int i = blockIdx.x * blockDim.x + threadIdx.x;
    if (i < n) {
        float acc = bias[i];
#pragma unroll
        for (int r = 0; r < REPLICAS; ++r)
            acc += g_rep[r * NODES + i];
        out[i] = acc;
    }
}

// Generic fallback for unexpected shapes.
__global__ __launch_bounds__(256) void scatter_fallback_kernel(
        const float* __restrict__ x,
        const float* __restrict__ ew,
        const int*   __restrict__ src,
        const int*   __restrict__ dst,
        float* __restrict__ out,
        int n) {
    const int stride = gridDim.x * blockDim.x;
    for (int e = blockIdx.x * blockDim.x + threadIdx.x; e < n; e += stride) {
        atomicAdd(&out[dst[e]], ew[e] * __ldg(&x[src[e]]));
    }
}

__global__ void init_out_kernel(const float* __restrict__ bias,
                                float* __restrict__ out, int n) {
    int i = blockIdx.x * blockDim.x + threadIdx.x;
    if (i < n) out[i] = bias[i];
}

extern "C" void kernel_launch(void* const* d_in, const int* in_sizes, int n_in,
                              void* d_out, int out_size) {
    const float* x    = (const float*)d_in[0];
    const float* ew   = (const float*)d_in[1];
    const float* bias = (const float*)d_in[2];
    const int*   src  = (const int*)d_in[3];
    const int*   dst  = (const int*)d_in[4];
    float* out = (float*)d_out;

    const int n_nodes = in_sizes[0];
    const int n_edges = in_sizes[1];

    if (n_nodes == NODES) {
        // 1) zero the replicas
        {
            int n4 = (REPLICAS * NODES) / 4;
            zero_rep_kernel<<<(n4 + 255) / 256, 256>>>();
        }
        // 2) scatter into replicas
        {
            int threads = 256;
            int blocks  = 2048;
            int n4 = n_edges >> 2;
            int max_blocks = (n4 + threads - 1) / threads;
            if (blocks > max_blocks) blocks = max_blocks;
            if (blocks < 1) blocks = 1;
            scatter_rep_kernel<<<blocks, threads>>>(x, ew, src, dst, n_edges);
        }
        // 3) out = bias + sum of replicas
        reduce_rep_kernel<<<(NODES + 255) / 256, 256>>>(bias, out, NODES);
    } else {
        init_out_kernel<<<(n_nodes + 255) / 256, 256>>>(bias, out, n_nodes);
        int threads = 256;
        int blocks  = 2048;
        int max_blocks = (n_edges + threads - 1) / threads;
        if (blocks > max_blocks) blocks = max_blocks;
        if (blocks < 1) blocks = 1;
        scatter_fallback_kernel<<<blocks, threads>>>(x, ew, src, dst, out, n_edges);
    }
}

// round 5
// speedup vs baseline: 1.4063x; 1.1850x over previous
#include <cuda_runtime.h>
#include <cuda_bf16.h>

// Inputs (metadata order):
//   d_in[0] = x            float32 [65536]
//   d_in[1] = edge_weights float32 [16777216]
//   d_in[2] = bias         float32 [65536]
//   d_in[3] = src          int32   [16777216]
//   d_in[4] = dst          int32   [16777216]
// Output: out[i] = bias[i] + sum_{e: dst[e]==i} x[src[e]]*edge_weights[e]
//
// R5: remove the random-LDG gather cost from the L1tex path (32 wavefronts
// per warp-gather). Keep 224KB of x in smem -> 87.5% of gathers are LDS
// (~free), 12.5% stay LDG. Keep replicated global accumulators (32 replicas,
// 8MB, L2-resident) to spread LTS RMW contention. Single streaming pass.

#define NODES      65536
#define REPLICAS   32
#define SMEM_NODES 57344              // 224KB of x in smem
#define SMEM_BYTES (SMEM_NODES * 4)

__device__ float g_rep[REPLICAS * NODES];   // 8MB scratch

__global__ void zero_rep_kernel() {
    int i = blockIdx.x * blockDim.x + threadIdx.x;
    float4* p = reinterpret_cast<float4*>(g_rep);
    int n4 = (REPLICAS * NODES) / 4;
    int stride = gridDim.x * blockDim.x;
    for (; i < n4; i += stride) p[i] = make_float4(0.f, 0.f, 0.f, 0.f);
}

__global__ __launch_bounds__(1024) void scatter_smem_rep_kernel(
        const float* __restrict__ x,
        const float* __restrict__ ew,
        const int*   __restrict__ src,
        const int*   __restrict__ dst,
        int n) {
    extern __shared__ float sx[];   // 57344 floats

    // Cooperative coalesced load of x[0 .. SMEM_NODES) into smem.
    {
        const float4* x4 = reinterpret_cast<const float4*>(x);
        float4* sx4 = reinterpret_cast<float4*>(sx);
        for (int i = threadIdx.x; i < SMEM_NODES / 4; i += blockDim.x)
            sx4[i] = x4[i];
    }
    __syncthreads();

    const int n4 = n >> 2;
    const float4* __restrict__ ew4 = reinterpret_cast<const float4*>(ew);
    const int4*   __restrict__ s4  = reinterpret_cast<const int4*>(src);
    const int4*   __restrict__ d4  = reinterpret_cast<const int4*>(dst);

    // Replica fixed per warp, decorrelated across warps/CTAs.
    const int warp = threadIdx.x >> 5;
    float* rep = g_rep + ((blockIdx.x * 32 + warp) & (REPLICAS - 1)) * NODES;

    const int stride = gridDim.x * blockDim.x;
    const int gtid   = blockIdx.x * blockDim.x + threadIdx.x;

    for (int i = gtid; i < n4; i += stride) {
        int4   s = __ldcs(&s4[i]);
        float4 w = __ldcs(&ew4[i]);
        int4   d = __ldcs(&d4[i]);

        // Gather: smem for the low 87.5% of node ids, global for the rest.
        int c0 = (s.x < SMEM_NODES) ? s.x : 0;
        int c1 = (s.y < SMEM_NODES) ? s.y : 0;
        int c2 = (s.z < SMEM_NODES) ? s.z : 0;
        int c3 = (s.w < SMEM_NODES) ? s.w : 0;
        float x0 = sx[c0];
        float x1 = sx[c1];
        float x2 = sx[c2];
        float x3 = sx[c3];
        if (s.x >= SMEM_NODES) x0 = __ldg(&x[s.x]);
        if (s.y >= SMEM_NODES) x1 = __ldg(&x[s.y]);
        if (s.z >= SMEM_NODES) x2 = __ldg(&x[s.z]);
        if (s.w >= SMEM_NODES) x3 = __ldg(&x[s.w]);

        atomicAdd(&rep[d.x], w.x * x0);
        atomicAdd(&rep[d.y], w.y * x1);
        atomicAdd(&rep[d.z], w.z * x2);
        atomicAdd(&rep[d.w], w.w * x3);
    }

    // Tail (n % 4)
    for (int e = (n4 << 2) + gtid; e < n; e += stride) {
        int s = src[e];
        float xv = (s < SMEM_NODES) ? sx[s] : __ldg(&x[s]);
        atomicAdd(&rep[dst[e]], ew[e] * xv);
    }
}

__global__ void reduce_rep_kernel(const float* __restrict__ bias,
                                  float* __restrict__ out, int n) {
    int i = blockIdx.x * blockDim.x + threadIdx.x;
    if (i < n) {
        float acc = bias[i];
#pragma unroll
        for (int r = 0; r < REPLICAS; ++r)
            acc += g_rep[r * NODES + i];
        out[i] = acc;
    }
}

// Generic fallback for unexpected shapes.
__global__ __launch_bounds__(256) void scatter_fallback_kernel(
        const float* __restrict__ x,
        const float* __restrict__ ew,
        const int*   __restrict__ src,
        const int*   __restrict__ dst,
        float* __restrict__ out,
        int n) {
    const int stride = gridDim.x * blockDim.x;
    for (int e = blockIdx.x * blockDim.x + threadIdx.x; e < n; e += stride) {
        atomicAdd(&out[dst[e]], ew[e] * __ldg(&x[src[e]]));
    }
}

__global__ void init_out_kernel(const float* __restrict__ bias,
                                float* __restrict__ out, int n) {
    int i = blockIdx.x * blockDim.x + threadIdx.x;
    if (i < n) out[i] = bias[i];
}

extern "C" void kernel_launch(void* const* d_in, const int* in_sizes, int n_in,
                              void* d_out, int out_size) {
    const float* x    = (const float*)d_in[0];
    const float* ew   = (const float*)d_in[1];
    const float* bias = (const float*)d_in[2];
    const int*   src  = (const int*)d_in[3];
    const int*   dst  = (const int*)d_in[4];
    float* out = (float*)d_out;

    const int n_nodes = in_sizes[0];
    const int n_edges = in_sizes[1];

    if (n_nodes == NODES) {
        // 1) zero the replicas (8MB)
        zero_rep_kernel<<<1024, 256>>>();

        // 2) scatter into replicas, x mostly smem-resident
        {
            static bool attr_set = false;
            if (!attr_set) {
                cudaFuncSetAttribute(scatter_smem_rep_kernel,
                                     cudaFuncAttributeMaxDynamicSharedMemorySize,
                                     SMEM_BYTES);
                attr_set = true;
            }
            scatter_smem_rep_kernel<<<148, 1024, SMEM_BYTES>>>(
                x, ew, src, dst, n_edges);
        }

        // 3) out = bias + sum of replicas
        reduce_rep_kernel<<<(NODES + 255) / 256, 256>>>(bias, out, NODES);
    } else {
        init_out_kernel<<<(n_nodes + 255) / 256, 256>>>(bias, out, n_nodes);
        int threads = 256;
        int blocks  = 2048;
        int max_blocks = (n_edges + threads - 1) / threads;
        if (blocks > max_blocks) blocks = max_blocks;
        if (blocks < 1) blocks = 1;
        scatter_fallback_kernel<<<blocks, threads>>>(x, ew, src, dst, out, n_edges);
    }
}